// round 13
// baseline (speedup 1.0000x reference)
#include <cuda_runtime.h>
#include <cuda_bf16.h>
#include <stdint.h>

// out_f32[4096, 4096] = bf16round( x_bf16[4096,4096] @ W_bf16[4096,4096]^T + bias )
// d_out dtype is FLOAT32 (bf16 values widened).
#define TOKENS 4096
#define KDIM   4096
#define NDIM   4096

// 128x128 CTA tile, BK=64, 8 warps (4m x 2n), warp tile 32x64, 2 CTA/SM,
// persistent CTAs. A: direct LDG->register fragments (no SMEM traffic).
// B: cp.async 4-stage pipeline + ldmatrix.
#define BM 128
#define BN 128
#define BK 64
#define KT_PER_TILE (KDIM / BK)       // 64
#define N_TILES ((TOKENS / BM) * (NDIM / BN))   // 1024
#define GRID_P 304                    // 2 per SM on 152 SMs
#define STAGES 4
#define B_STAGE 16384                 // 128 rows x 128B
#define SMEM_TOTAL (STAGES * B_STAGE) // 65536 -> 2 CTAs/SM

// Scratch: pre-converted bf16 operands (__device__ globals; no allocs)
__device__ __align__(256) __nv_bfloat16 g_x[(size_t)TOKENS * KDIM];
__device__ __align__(256) __nv_bfloat16 g_w[(size_t)NDIM * KDIM];

// ---------------- helpers ----------------
static __device__ __forceinline__ uint32_t smem_u32(const void* p) {
    uint32_t a;
    asm("{ .reg .u64 t; cvta.to.shared.u64 t, %1; cvt.u32.u64 %0, t; }" : "=r"(a) : "l"(p));
    return a;
}
static __device__ __forceinline__ void cp_async16(uint32_t smem_dst, uint64_t gsrc) {
    asm volatile("cp.async.cg.shared.global [%0], [%1], 16;"
                 :: "r"(smem_dst), "l"(gsrc) : "memory");
}
static __device__ __forceinline__ uint32_t ldg_u32(uint64_t addr) {
    uint32_t v;
    asm volatile("ld.global.nc.u32 %0, [%1];" : "=r"(v) : "l"(addr));
    return v;
}
static __device__ __forceinline__ uint32_t pack_bf162(float a, float b) {
    __nv_bfloat162 p;
    p.x = __float2bfloat16(a); p.y = __float2bfloat16(b);
    return *reinterpret_cast<uint32_t*>(&p);
}

// ---------------- fused conversion kernel ----------------
#define X_U4 ((size_t)TOKENS * KDIM / 8)
#define W_U4 ((size_t)NDIM * KDIM / 8)
__global__ void cvt_all_kernel(const float* __restrict__ x,
                               const float* __restrict__ w,
                               const float* __restrict__ scale) {
    const size_t total = X_U4 + W_U4;
    const size_t stride = (size_t)gridDim.x * blockDim.x;
    const float4* __restrict__ x4 = reinterpret_cast<const float4*>(x);
    const float4* __restrict__ w4 = reinterpret_cast<const float4*>(w);
    uint4* __restrict__ ox = reinterpret_cast<uint4*>(g_x);
    uint4* __restrict__ ow = reinterpret_cast<uint4*>(g_w);
    for (size_t i = (size_t)blockIdx.x * blockDim.x + threadIdx.x; i < total; i += stride) {
        if (i < X_U4) {
            float4 v0 = __ldg(&x4[2 * i]);
            float4 v1 = __ldg(&x4[2 * i + 1]);
            uint4 o;
            o.x = pack_bf162(v0.x, v0.y); o.y = pack_bf162(v0.z, v0.w);
            o.z = pack_bf162(v1.x, v1.y); o.w = pack_bf162(v1.z, v1.w);
            ox[i] = o;
        } else {
            size_t j = i - X_U4;
            int row = (int)(j >> 9);
            // reference: bf16(fp8_val) * bf16(scale) in bf16; fp8 vals exact in
            // f32, so f32 multiply + single bf16 round is identical.
            float s = __bfloat162float(__float2bfloat16(__ldg(&scale[row])));
            float4 v0 = __ldg(&w4[2 * j]);
            float4 v1 = __ldg(&w4[2 * j + 1]);
            uint4 o;
            o.x = pack_bf162(v0.x * s, v0.y * s); o.y = pack_bf162(v0.z * s, v0.w * s);
            o.z = pack_bf162(v1.x * s, v1.y * s); o.w = pack_bf162(v1.z * s, v1.w * s);
            ow[j] = o;
        }
    }
}

// ---------------- persistent mma.sync bf16 GEMM ----------------
__global__ void __launch_bounds__(256, 2)
fp8lin_gemm(const float* __restrict__ bias, float* __restrict__ out) {
    extern __shared__ char smem[];
    const uint32_t sb = smem_u32(smem);
    const int tid = threadIdx.x;
    const int wid = tid >> 5, lane = tid & 31;
    const int wm = wid >> 1, wn = wid & 1;         // 4x2 warp grid, warp tile 32x64
    const int bid = blockIdx.x;

    uint64_t baseA, baseB;
    {
        const void* pa = g_x;
        const void* pb = g_w;
        asm("cvta.to.global.u64 %0, %1;" : "=l"(baseA) : "l"(pa));
        asm("cvta.to.global.u64 %0, %1;" : "=l"(baseB) : "l"(pb));
    }

    const int ntiles = (N_TILES - 1 - bid) / GRID_P + 1;
    const int total_chunks = ntiles * KT_PER_TILE;

    // ---- B stage loader (cp.async, 1024 16B chunks, 4/thread) ----
    // SMEM rows 128B, Swizzle<3,4,3>: 16B-chunk ^= (row&7).
    auto load_chunk_b = [&](int c) {
        const int t = bid + (c >> 6) * GRID_P;
        const int kt = c & 63;
        const uint64_t gB = baseB + ((uint64_t)(t & 31) << 20);
        const uint32_t sB = sb + (uint32_t)(c & (STAGES - 1)) * B_STAGE;
        const uint64_t koff = (uint64_t)kt * (BK * 2);
        #pragma unroll
        for (int it = 0; it < 4; ++it) {
            int idx = tid + it * 256;
            int row = idx >> 3, ch = idx & 7;
            uint32_t so = ((uint32_t)row << 7) | (uint32_t)((ch << 4) ^ ((row & 7) << 4));
            cp_async16(sB + so, gB + (uint64_t)row * (KDIM * 2) + koff + (uint64_t)(ch << 4));
        }
        asm volatile("cp.async.commit_group;" ::: "memory");
    };

    // ---- A fragment LDG addressing ----
    // Per thread, fragment reg i of tile mt at k-step ks:
    //   row = wm*32 + mt*16 + (i&1)*8 + lane/4
    //   colB = ks*32 + (i>>1)*16 + (lane&3)*4          (bytes within 128B k-chunk)
    // Per-thread constant offsets into the A panel:
    const uint32_t offA0 = (uint32_t)((wm * 32 + 0 * 16 + (lane >> 2)) * (KDIM * 2) + (lane & 3) * 4);
    const uint32_t offA1 = (uint32_t)((wm * 32 + 1 * 16 + (lane >> 2)) * (KDIM * 2) + (lane & 3) * 4);
    #define A_R8 ((uint64_t)(8 * KDIM * 2))   // +8 rows

    // ---- B ldmatrix address components (unchanged from R11) ----
    const int j8 = lane >> 3, i8 = lane & 7;
    uint32_t bP[4], bX[4];
    #pragma unroll
    for (int g = 0; g < 4; ++g) {
        int r = wn * 64 + g * 16 + ((j8 >> 1) & 1) * 8 + i8;
        bP[g] = (uint32_t)r << 7;
        bX[g] = (uint32_t)((r & 7) << 4);
    }
    const uint32_t bK = (uint32_t)((j8 & 1) << 4);

    float acc[2][8][4];
    #pragma unroll
    for (int mt = 0; mt < 2; ++mt)
        #pragma unroll
        for (int nt = 0; nt < 8; ++nt)
            #pragma unroll
            for (int q = 0; q < 4; ++q) acc[mt][nt][q] = 0.0f;

    const int g4 = lane >> 2, tig = lane & 3;

    // A fragment double buffer: aR[buf][mt*4 + i]
    uint32_t aR[2][8];
    // current chunk A addresses (panel + kt*128 + thread offset), per tile
    uint64_t aCur0 = baseA + ((uint64_t)(bid >> 5) << 20) + offA0;
    uint64_t aCur1 = baseA + ((uint64_t)(bid >> 5) << 20) + offA1;

    auto ldg_afrag = [&](uint32_t* dst, uint64_t a0, uint64_t a1, int ks) {
        const uint64_t k0 = (uint64_t)(ks * 32);
        dst[0] = ldg_u32(a0 + k0);
        dst[1] = ldg_u32(a0 + k0 + A_R8);
        dst[2] = ldg_u32(a0 + k0 + 16);
        dst[3] = ldg_u32(a0 + k0 + A_R8 + 16);
        dst[4] = ldg_u32(a1 + k0);
        dst[5] = ldg_u32(a1 + k0 + A_R8);
        dst[6] = ldg_u32(a1 + k0 + 16);
        dst[7] = ldg_u32(a1 + k0 + A_R8 + 16);
    };

    load_chunk_b(0);
    load_chunk_b(1);
    load_chunk_b(2);
    ldg_afrag(aR[0], aCur0, aCur1, 0);   // bootstrap A(c=0, ks=0)

    #pragma unroll 1
    for (int c = 0; c < total_chunks; ++c) {
        // B stage c ready when <=2 groups pending (c+1, c+2 may be in flight).
        asm volatile("cp.async.wait_group 2;" ::: "memory");
        // Single barrier: publishes stage c AND proves stage (c+3)%4 == (c-1)%4
        // drained (all warps finished reading it).
        __syncthreads();
        if (c + 3 < total_chunks) load_chunk_b(c + 3);

        const uint32_t sB = sb + (uint32_t)(c & (STAGES - 1)) * B_STAGE;

        #pragma unroll
        for (int ks = 0; ks < 4; ++ks) {
            const int cur = ks & 1, nxt = cur ^ 1;
            // Prefetch next A fragments (registers; no barrier dependency).
            if (ks < 3) {
                ldg_afrag(aR[nxt], aCur0, aCur1, ks + 1);
            } else if (c + 1 < total_chunks) {
                const int nc = c + 1;
                const int t2 = bid + (nc >> 6) * GRID_P;
                const uint64_t pan = baseA + ((uint64_t)(t2 >> 5) << 20)
                                   + (uint64_t)(nc & 63) * 128;
                aCur0 = pan + offA0;
                aCur1 = pan + offA1;
                ldg_afrag(aR[nxt], aCur0, aCur1, 0);
            }

            const uint32_t kb = (uint32_t)(ks << 5);
            uint32_t b[4][4];
            #pragma unroll
            for (int g = 0; g < 4; ++g) {
                uint32_t addr = sB + bP[g] + ((kb + bK) ^ bX[g]);
                asm volatile("ldmatrix.sync.aligned.m8n8.x4.shared.b16 {%0,%1,%2,%3}, [%4];"
                             : "=r"(b[g][0]), "=r"(b[g][1]), "=r"(b[g][2]), "=r"(b[g][3])
                             : "r"(addr));
            }
            #pragma unroll
            for (int mt = 0; mt < 2; ++mt) {
                const uint32_t* af = &aR[cur][mt * 4];
                #pragma unroll
                for (int nt = 0; nt < 8; ++nt) {
                    const uint32_t b0 = b[nt >> 1][(nt & 1) * 2];
                    const uint32_t b1 = b[nt >> 1][(nt & 1) * 2 + 1];
                    asm volatile(
                        "mma.sync.aligned.m16n8k16.row.col.f32.bf16.bf16.f32 "
                        "{%0,%1,%2,%3}, {%4,%5,%6,%7}, {%8,%9}, {%0,%1,%2,%3};"
                        : "+f"(acc[mt][nt][0]), "+f"(acc[mt][nt][1]),
                          "+f"(acc[mt][nt][2]), "+f"(acc[mt][nt][3])
                        : "r"(af[0]), "r"(af[1]), "r"(af[2]), "r"(af[3]),
                          "r"(b0), "r"(b1));
                }
            }
        }

        // ---- tile boundary: epilogue (registers + gmem only; no barrier).
        if ((c & 63) == 63) {
            const int t = bid + (c >> 6) * GRID_P;
            const int m0 = (t >> 5) * BM, n0 = (t & 31) * BN;
            #pragma unroll
            for (int nt = 0; nt < 8; ++nt) {
                const int col = n0 + wn * 64 + nt * 8 + tig * 2;
                const __nv_bfloat16 bz0 = __float2bfloat16(__ldg(&bias[col]));
                const __nv_bfloat16 bz1 = __float2bfloat16(__ldg(&bias[col + 1]));
                #pragma unroll
                for (int mt = 0; mt < 2; ++mt) {
                    const int r0 = m0 + wm * 32 + mt * 16 + g4;
                    float2 v0, v1;
                    v0.x = __bfloat162float(__hadd(__float2bfloat16(acc[mt][nt][0]), bz0));
                    v0.y = __bfloat162float(__hadd(__float2bfloat16(acc[mt][nt][1]), bz1));
                    v1.x = __bfloat162float(__hadd(__float2bfloat16(acc[mt][nt][2]), bz0));
                    v1.y = __bfloat162float(__hadd(__float2bfloat16(acc[mt][nt][3]), bz1));
                    *reinterpret_cast<float2*>(out + (size_t)r0 * NDIM + col) = v0;
                    *reinterpret_cast<float2*>(out + (size_t)(r0 + 8) * NDIM + col) = v1;
                    acc[mt][nt][0] = 0.0f; acc[mt][nt][1] = 0.0f;
                    acc[mt][nt][2] = 0.0f; acc[mt][nt][3] = 0.0f;
                }
            }
        }
    }
}

// ---------------- launch ----------------
extern "C" void kernel_launch(void* const* d_in, const int* in_sizes, int n_in,
                              void* d_out, int out_size) {
    const float* x     = (const float*)d_in[0];   // [2,2048,4096] f32
    const float* w     = (const float*)d_in[1];   // [4096,4096] f32 (fp8-representable)
    const float* scale = (const float*)d_in[2];   // [4096,1] f32
    const float* bias  = (const float*)d_in[3];   // [4096] f32
    float* out         = (float*)d_out;           // [2,2048,4096] f32 (bf16 values widened)

    cudaFuncSetAttribute(fp8lin_gemm, cudaFuncAttributeMaxDynamicSharedMemorySize, SMEM_TOTAL);

    cvt_all_kernel<<<4096, 256>>>(x, w, scale);

    fp8lin_gemm<<<GRID_P, 256, SMEM_TOTAL>>>(bias, out);
}

// round 14
// speedup vs baseline: 2.0574x; 2.0574x over previous
#include <cuda_runtime.h>
#include <cuda_bf16.h>
#include <stdint.h>

// out_f32[4096, 4096] = bf16round( x_bf16[4096,4096] @ W_bf16[4096,4096]^T + bias )
// d_out dtype is FLOAT32 (bf16 values widened).
#define TOKENS 4096
#define KDIM   4096
#define NDIM   4096

// 128x128 CTA tile, BK=64, 8 warps (4m x 2n), warp tile 32x64, 3 stages,
// 2 CTA/SM, persistent CTAs, single barrier per K-chunk. cp.async issue for
// chunk c+2 is deferred into the middle of chunk c's compute so the
// post-barrier critical path starts with LDSM/MMA immediately.
#define BM 128
#define BN 128
#define BK 64
#define KT_PER_TILE (KDIM / BK)       // 64
#define N_TILES ((TOKENS / BM) * (NDIM / BN))   // 1024
#define GRID_P 304                    // 2 per SM on 152 SMs
#define STAGES 3
#define A_STAGE 16384                 // 128 rows x 128B
#define STAGE_BYTES 32768             // A 16K + B 16K
#define SMEM_TOTAL (STAGES * STAGE_BYTES)   // 98304 -> 2 CTAs/SM

// Scratch: pre-converted bf16 operands (__device__ globals; no allocs)
__device__ __align__(256) __nv_bfloat16 g_x[(size_t)TOKENS * KDIM];
__device__ __align__(256) __nv_bfloat16 g_w[(size_t)NDIM * KDIM];

// ---------------- helpers ----------------
static __device__ __forceinline__ uint32_t smem_u32(const void* p) {
    uint32_t a;
    asm("{ .reg .u64 t; cvta.to.shared.u64 t, %1; cvt.u32.u64 %0, t; }" : "=r"(a) : "l"(p));
    return a;
}
static __device__ __forceinline__ void cp_async16(uint32_t smem_dst, uint64_t gsrc) {
    asm volatile("cp.async.cg.shared.global [%0], [%1], 16;"
                 :: "r"(smem_dst), "l"(gsrc) : "memory");
}
static __device__ __forceinline__ uint32_t pack_bf162(float a, float b) {
    __nv_bfloat162 p;
    p.x = __float2bfloat16(a); p.y = __float2bfloat16(b);
    return *reinterpret_cast<uint32_t*>(&p);
}

// ---------------- fused conversion kernel ----------------
#define X_U4 ((size_t)TOKENS * KDIM / 8)
#define W_U4 ((size_t)NDIM * KDIM / 8)
__global__ void cvt_all_kernel(const float* __restrict__ x,
                               const float* __restrict__ w,
                               const float* __restrict__ scale) {
    const size_t total = X_U4 + W_U4;
    const size_t stride = (size_t)gridDim.x * blockDim.x;
    const float4* __restrict__ x4 = reinterpret_cast<const float4*>(x);
    const float4* __restrict__ w4 = reinterpret_cast<const float4*>(w);
    uint4* __restrict__ ox = reinterpret_cast<uint4*>(g_x);
    uint4* __restrict__ ow = reinterpret_cast<uint4*>(g_w);
    for (size_t i = (size_t)blockIdx.x * blockDim.x + threadIdx.x; i < total; i += stride) {
        if (i < X_U4) {
            float4 v0 = __ldg(&x4[2 * i]);
            float4 v1 = __ldg(&x4[2 * i + 1]);
            uint4 o;
            o.x = pack_bf162(v0.x, v0.y); o.y = pack_bf162(v0.z, v0.w);
            o.z = pack_bf162(v1.x, v1.y); o.w = pack_bf162(v1.z, v1.w);
            ox[i] = o;
        } else {
            size_t j = i - X_U4;
            int row = (int)(j >> 9);
            // reference: bf16(fp8_val) * bf16(scale) in bf16; fp8 vals exact in
            // f32, so f32 multiply + single bf16 round is identical.
            float s = __bfloat162float(__float2bfloat16(__ldg(&scale[row])));
            float4 v0 = __ldg(&w4[2 * j]);
            float4 v1 = __ldg(&w4[2 * j + 1]);
            uint4 o;
            o.x = pack_bf162(v0.x * s, v0.y * s); o.y = pack_bf162(v0.z * s, v0.w * s);
            o.z = pack_bf162(v1.x * s, v1.y * s); o.w = pack_bf162(v1.z * s, v1.w * s);
            ow[j] = o;
        }
    }
}

// ---------------- persistent mma.sync bf16 GEMM ----------------
__global__ void __launch_bounds__(256, 2)
fp8lin_gemm(const float* __restrict__ bias, float* __restrict__ out) {
    extern __shared__ char smem[];
    const uint32_t sb = smem_u32(smem);
    const int tid = threadIdx.x;
    const int wid = tid >> 5, lane = tid & 31;
    const int wm = wid >> 1, wn = wid & 1;         // 4x2 warp grid, warp tile 32x64
    const int bid = blockIdx.x;

    uint64_t baseA, baseB;
    {
        const void* pa = g_x;
        const void* pb = g_w;
        asm("cvta.to.global.u64 %0, %1;" : "=l"(baseA) : "l"(pa));
        asm("cvta.to.global.u64 %0, %1;" : "=l"(baseB) : "l"(pb));
    }

    const int ntiles = (N_TILES - 1 - bid) / GRID_P + 1;
    const int total_chunks = ntiles * KT_PER_TILE;

    // Per-thread constant loader offsets (computed once).
    const int lrow = tid >> 3, lch = tid & 7;
    const uint32_t sOffBase = ((uint32_t)lrow << 7) | (uint32_t)((lch << 4) ^ ((lrow & 7) << 4));
    const uint64_t gOffBase = (uint64_t)lrow * (KDIM * 2) + (uint64_t)(lch << 4);
    #define ROW_STRIDE_32 ((uint64_t)32 * KDIM * 2)

    // Issue A-half of chunk c: rows 0..127 of the A tile (4 x 32-row slabs).
    auto load_chunk_A = [&](int c) {
        const int t = bid + (c >> 6) * GRID_P;
        const uint64_t gA = baseA + ((uint64_t)(t >> 5) << 20)
                          + (uint64_t)(c & 63) * 128 + gOffBase;
        const uint32_t sA = sb + (uint32_t)(c % STAGES) * STAGE_BYTES + sOffBase;
        #pragma unroll
        for (int it = 0; it < 4; ++it)
            cp_async16(sA + (uint32_t)(it << 12), gA + (uint64_t)it * ROW_STRIDE_32);
    };
    // Issue B-half of chunk c and commit the (A+B) group.
    auto load_chunk_B = [&](int c) {
        const int t = bid + (c >> 6) * GRID_P;
        const uint64_t gB = baseB + ((uint64_t)(t & 31) << 20)
                          + (uint64_t)(c & 63) * 128 + gOffBase;
        const uint32_t sB = sb + (uint32_t)(c % STAGES) * STAGE_BYTES + A_STAGE + sOffBase;
        #pragma unroll
        for (int it = 0; it < 4; ++it)
            cp_async16(sB + (uint32_t)(it << 12), gB + (uint64_t)it * ROW_STRIDE_32);
        asm volatile("cp.async.commit_group;" ::: "memory");
    };

    // ldmatrix per-thread address components.
    const int j8 = lane >> 3, i8 = lane & 7;
    uint32_t aP[2], aX[2];
    #pragma unroll
    for (int mt = 0; mt < 2; ++mt) {
        int r = wm * 32 + mt * 16 + (j8 & 1) * 8 + i8;
        aP[mt] = (uint32_t)r << 7;
        aX[mt] = (uint32_t)((r & 7) << 4);
    }
    const uint32_t aK = (uint32_t)((j8 >> 1) << 4);
    uint32_t bP[4], bX[4];
    #pragma unroll
    for (int g = 0; g < 4; ++g) {
        int r = wn * 64 + g * 16 + ((j8 >> 1) & 1) * 8 + i8;
        bP[g] = (uint32_t)r << 7;
        bX[g] = (uint32_t)((r & 7) << 4);
    }
    const uint32_t bK = (uint32_t)((j8 & 1) << 4);

    float acc[2][8][4];
    #pragma unroll
    for (int mt = 0; mt < 2; ++mt)
        #pragma unroll
        for (int nt = 0; nt < 8; ++nt)
            #pragma unroll
            for (int q = 0; q < 4; ++q) acc[mt][nt][q] = 0.0f;

    const int g4 = lane >> 2, tig = lane & 3;

    load_chunk_A(0); load_chunk_B(0);
    load_chunk_A(1); load_chunk_B(1);

    #pragma unroll 1
    for (int c = 0; c < total_chunks; ++c) {
        // Committed groups: 0..c+1. wait_group 1 -> group c complete.
        if (c + 1 < total_chunks) {
            asm volatile("cp.async.wait_group 1;" ::: "memory");
        } else {
            asm volatile("cp.async.wait_group 0;" ::: "memory");
        }
        // Single barrier: publishes chunk c AND proves stage (c+2)%3 == (c-1)%3
        // drained by all warps.
        __syncthreads();

        const uint32_t sA = sb + (uint32_t)(c % STAGES) * STAGE_BYTES;
        const uint32_t sB = sA + A_STAGE;
        const bool more = (c + 2 < total_chunks);

        #pragma unroll
        for (int ks = 0; ks < 4; ++ks) {
            const uint32_t kb = (uint32_t)(ks << 5);
            uint32_t a[2][4], b[4][4];
            #pragma unroll
            for (int mt = 0; mt < 2; ++mt) {
                uint32_t addr = sA + aP[mt] + ((kb + aK) ^ aX[mt]);
                asm volatile("ldmatrix.sync.aligned.m8n8.x4.shared.b16 {%0,%1,%2,%3}, [%4];"
                             : "=r"(a[mt][0]), "=r"(a[mt][1]), "=r"(a[mt][2]), "=r"(a[mt][3])
                             : "r"(addr));
            }
            #pragma unroll
            for (int g = 0; g < 4; ++g) {
                uint32_t addr = sB + bP[g] + ((kb + bK) ^ bX[g]);
                asm volatile("ldmatrix.sync.aligned.m8n8.x4.shared.b16 {%0,%1,%2,%3}, [%4];"
                             : "=r"(b[g][0]), "=r"(b[g][1]), "=r"(b[g][2]), "=r"(b[g][3])
                             : "r"(addr));
            }
            #pragma unroll
            for (int mt = 0; mt < 2; ++mt) {
                #pragma unroll
                for (int nt = 0; nt < 8; ++nt) {
                    const uint32_t b0 = b[nt >> 1][(nt & 1) * 2];
                    const uint32_t b1 = b[nt >> 1][(nt & 1) * 2 + 1];
                    asm volatile(
                        "mma.sync.aligned.m16n8k16.row.col.f32.bf16.bf16.f32 "
                        "{%0,%1,%2,%3}, {%4,%5,%6,%7}, {%8,%9}, {%0,%1,%2,%3};"
                        : "+f"(acc[mt][nt][0]), "+f"(acc[mt][nt][1]),
                          "+f"(acc[mt][nt][2]), "+f"(acc[mt][nt][3])
                        : "r"(a[mt][0]), "r"(a[mt][1]), "r"(a[mt][2]), "r"(a[mt][3]),
                          "r"(b0), "r"(b1));
                }
            }
            // Deferred cp.async issue for chunk c+2: A-half after ks=0's MMAs
            // are queued, B-half (+commit) after ks=1. The tensor pipe chews on
            // the queued MMAs while the LSU issues these.
            if (ks == 0 && more) load_chunk_A(c + 2);
            if (ks == 1 && more) load_chunk_B(c + 2);
        }

        // ---- tile boundary: epilogue (registers + gmem only; no barrier).
        if ((c & 63) == 63) {
            const int t = bid + (c >> 6) * GRID_P;
            const int m0 = (t >> 5) * BM, n0 = (t & 31) * BN;
            #pragma unroll
            for (int nt = 0; nt < 8; ++nt) {
                const int col = n0 + wn * 64 + nt * 8 + tig * 2;
                const __nv_bfloat16 bz0 = __float2bfloat16(__ldg(&bias[col]));
                const __nv_bfloat16 bz1 = __float2bfloat16(__ldg(&bias[col + 1]));
                #pragma unroll
                for (int mt = 0; mt < 2; ++mt) {
                    const int r0 = m0 + wm * 32 + mt * 16 + g4;
                    float2 v0, v1;
                    v0.x = __bfloat162float(__hadd(__float2bfloat16(acc[mt][nt][0]), bz0));
                    v0.y = __bfloat162float(__hadd(__float2bfloat16(acc[mt][nt][1]), bz1));
                    v1.x = __bfloat162float(__hadd(__float2bfloat16(acc[mt][nt][2]), bz0));
                    v1.y = __bfloat162float(__hadd(__float2bfloat16(acc[mt][nt][3]), bz1));
                    *reinterpret_cast<float2*>(out + (size_t)r0 * NDIM + col) = v0;
                    *reinterpret_cast<float2*>(out + (size_t)(r0 + 8) * NDIM + col) = v1;
                    acc[mt][nt][0] = 0.0f; acc[mt][nt][1] = 0.0f;
                    acc[mt][nt][2] = 0.0f; acc[mt][nt][3] = 0.0f;
                }
            }
        }
    }
}

// ---------------- launch ----------------
extern "C" void kernel_launch(void* const* d_in, const int* in_sizes, int n_in,
                              void* d_out, int out_size) {
    const float* x     = (const float*)d_in[0];   // [2,2048,4096] f32
    const float* w     = (const float*)d_in[1];   // [4096,4096] f32 (fp8-representable)
    const float* scale = (const float*)d_in[2];   // [4096,1] f32
    const float* bias  = (const float*)d_in[3];   // [4096] f32
    float* out         = (float*)d_out;           // [2,2048,4096] f32 (bf16 values widened)

    cudaFuncSetAttribute(fp8lin_gemm, cudaFuncAttributeMaxDynamicSharedMemorySize, SMEM_TOTAL);

    cvt_all_kernel<<<4096, 256>>>(x, w, scale);

    fp8lin_gemm<<<GRID_P, 256, SMEM_TOTAL>>>(bias, out);
}